// round 1
// baseline (speedup 1.0000x reference)
#include <cuda_runtime.h>
#include <math.h>

// Problem constants (fixed shapes for RNN_11828339933262)
#define BATCH 4
#define SEQ   2048
#define DIM   2048          // D_IN == D_STATE == D_OUT
#define NHEADS 32
#define HDIM  64
#define MTOT  (BATCH * SEQ) // 8192 rows

// Scratch (device globals: allocation-free)
__device__ float g_h[(size_t)MTOT * DIM];   // input-projection output
__device__ float g_s[(size_t)MTOT * DIM];   // rnn states, then rmsnorm'd in place

// ---------------------------------------------------------------------------
// SGEMM: C[m][n] = (bias?bias[n]:0) + sum_k A[m][k] * B[n][k]
// A: (M,K) row-major, B: (N,K) row-major ("NT" layout: both K-contiguous)
// BM=BN=128, BK=8, TM=TN=8, 256 threads
// ---------------------------------------------------------------------------
#define BM 128
#define BN 128
#define BK 8
#define TM 8
#define TN 8

__device__ __forceinline__ void sgemm_body(
    const float* __restrict__ A, const float* __restrict__ B,
    const float* __restrict__ bias, float* __restrict__ C,
    int M, int N, int K)
{
    __shared__ float As[BK][BM + 4];
    __shared__ float Bs[BK][BN + 4];

    const int tid  = threadIdx.x;
    const int cRow = blockIdx.y * BM;
    const int cCol = blockIdx.x * BN;
    const int tx = tid % 16;       // 16 col-tiles of TN=8
    const int ty = tid / 16;       // 16 row-tiles of TM=8

    const int lRow = tid >> 1;         // 0..127
    const int lCol = (tid & 1) * 4;    // 0 or 4

    const float* Aptr = A + (size_t)cRow * K;
    const float* Bptr = B + (size_t)cCol * K;

    float acc[TM][TN];
#pragma unroll
    for (int i = 0; i < TM; i++)
#pragma unroll
        for (int j = 0; j < TN; j++) acc[i][j] = 0.f;

    for (int k0 = 0; k0 < K; k0 += BK) {
        float4 va = *(const float4*)(Aptr + (size_t)lRow * K + k0 + lCol);
        float4 vb = *(const float4*)(Bptr + (size_t)lRow * K + k0 + lCol);
        As[lCol + 0][lRow] = va.x;
        As[lCol + 1][lRow] = va.y;
        As[lCol + 2][lRow] = va.z;
        As[lCol + 3][lRow] = va.w;
        Bs[lCol + 0][lRow] = vb.x;
        Bs[lCol + 1][lRow] = vb.y;
        Bs[lCol + 2][lRow] = vb.z;
        Bs[lCol + 3][lRow] = vb.w;
        __syncthreads();

#pragma unroll
        for (int k = 0; k < BK; k++) {
            float ra[TM], rb[TN];
#pragma unroll
            for (int i = 0; i < TM; i++) ra[i] = As[k][ty * TM + i];
#pragma unroll
            for (int j = 0; j < TN; j++) rb[j] = Bs[k][tx * TN + j];
#pragma unroll
            for (int i = 0; i < TM; i++)
#pragma unroll
                for (int j = 0; j < TN; j++)
                    acc[i][j] = fmaf(ra[i], rb[j], acc[i][j]);
        }
        __syncthreads();
    }

#pragma unroll
    for (int i = 0; i < TM; i++) {
        int row = cRow + ty * TM + i;
#pragma unroll
        for (int j = 0; j < TN; j++) {
            int col = cCol + tx * TN + j;
            float v = acc[i][j];
            if (bias) v += bias[col];
            C[(size_t)row * N + col] = v;
        }
    }
}

__global__ __launch_bounds__(256) void gemm_in_kernel(
    const float* __restrict__ x, const float* __restrict__ w_in,
    const float* __restrict__ b_in)
{
    sgemm_body(x, w_in, b_in, g_h, MTOT, DIM, DIM);
}

__global__ __launch_bounds__(256) void gemm_out_kernel(
    const float* __restrict__ w_out, float* __restrict__ out)
{
    sgemm_body(g_s, w_out, nullptr, out, MTOT, DIM, DIM);
}

// ---------------------------------------------------------------------------
// RNN scan: per (b, head): s_t = tanh(s_{t-1} @ W + x_t), write every state.
// One CTA per (b,n), 64 threads; thread j owns output element j with the
// j-th column of W resident in 64 registers. State ping-pongs in shared.
// ---------------------------------------------------------------------------
__global__ __launch_bounds__(64) void rnn_scan_kernel(
    const float* __restrict__ state_weight)
{
    const int b = blockIdx.x >> 5;
    const int n = blockIdx.x & 31;
    const int j = threadIdx.x;

    __shared__ float s_sh[2][HDIM];

    // W[n][k][j] for k=0..63 (coalesced across j per k)
    float Wc[HDIM];
    const float* Wn = state_weight + (size_t)n * HDIM * HDIM;
#pragma unroll
    for (int k = 0; k < HDIM; k++) Wc[k] = Wn[k * HDIM + j];

    s_sh[0][j] = 0.f;
    __syncthreads();

    const size_t base = ((size_t)b * SEQ) * DIM + n * HDIM + j;
    float xt = g_h[base];
    int cur = 0;

    for (int t = 0; t < SEQ; t++) {
        // prefetch next timestep's input
        float xn = (t + 1 < SEQ) ? g_h[base + (size_t)(t + 1) * DIM] : 0.f;

        const float4* sp = (const float4*)s_sh[cur];
        float a0 = 0.f, a1 = 0.f, a2 = 0.f, a3 = 0.f;
#pragma unroll
        for (int k4 = 0; k4 < HDIM / 4; k4++) {
            float4 v = sp[k4];
            a0 = fmaf(v.x, Wc[4 * k4 + 0], a0);
            a1 = fmaf(v.y, Wc[4 * k4 + 1], a1);
            a2 = fmaf(v.z, Wc[4 * k4 + 2], a2);
            a3 = fmaf(v.w, Wc[4 * k4 + 3], a3);
        }
        float sv = tanhf((a0 + a1) + (a2 + a3) + xt);
        s_sh[cur ^ 1][j] = sv;
        g_s[base + (size_t)t * DIM] = sv;
        xt = xn;
        cur ^= 1;
        __syncthreads();
    }
}

// ---------------------------------------------------------------------------
// RMSNorm in place on g_s: y *= rsqrt(mean(y^2)+eps) * norm_weight
// One block per row (8192 blocks), 256 threads, 8 floats/thread.
// ---------------------------------------------------------------------------
__global__ __launch_bounds__(256) void rmsnorm_kernel(
    const float* __restrict__ norm_weight)
{
    const int row = blockIdx.x;
    float* p = g_s + (size_t)row * DIM;
    const int t = threadIdx.x;

    float4 a = ((const float4*)p)[t];
    float4 b = ((const float4*)p)[t + 256];
    float ss = a.x * a.x + a.y * a.y + a.z * a.z + a.w * a.w
             + b.x * b.x + b.y * b.y + b.z * b.z + b.w * b.w;

    // warp reduce
#pragma unroll
    for (int off = 16; off > 0; off >>= 1)
        ss += __shfl_xor_sync(0xFFFFFFFFu, ss, off);

    __shared__ float red[8];
    const int warp = t >> 5;
    const int lane = t & 31;
    if (lane == 0) red[warp] = ss;
    __syncthreads();
    float total;
    if (warp == 0) {
        float v = (lane < 8) ? red[lane] : 0.f;
#pragma unroll
        for (int off = 4; off > 0; off >>= 1)
            v += __shfl_xor_sync(0xFFFFFFFFu, v, off);
        if (lane == 0) red[0] = v;
    }
    __syncthreads();
    total = red[0];

    const float scale = rsqrtf(total * (1.0f / DIM) + 1e-6f);

    float4 ga = ((const float4*)norm_weight)[t];
    float4 gb = ((const float4*)norm_weight)[t + 256];
    a.x *= scale * ga.x; a.y *= scale * ga.y; a.z *= scale * ga.z; a.w *= scale * ga.w;
    b.x *= scale * gb.x; b.y *= scale * gb.y; b.z *= scale * gb.z; b.w *= scale * gb.w;
    ((float4*)p)[t]       = a;
    ((float4*)p)[t + 256] = b;
}

// ---------------------------------------------------------------------------
// Launch
// ---------------------------------------------------------------------------
extern "C" void kernel_launch(void* const* d_in, const int* in_sizes, int n_in,
                              void* d_out, int out_size)
{
    const float* x            = (const float*)d_in[0];
    const float* w_in         = (const float*)d_in[1];
    const float* b_in         = (const float*)d_in[2];
    const float* state_weight = (const float*)d_in[3];
    const float* norm_weight  = (const float*)d_in[4];
    const float* w_out        = (const float*)d_in[5];
    float* out = (float*)d_out;

    dim3 gemm_grid(DIM / BN, MTOT / BM);   // (16, 64)

    gemm_in_kernel<<<gemm_grid, 256>>>(x, w_in, b_in);
    rnn_scan_kernel<<<BATCH * NHEADS, 64>>>(state_weight);
    rmsnorm_kernel<<<MTOT, 256>>>(norm_weight);
    gemm_out_kernel<<<gemm_grid, 256>>>(w_out, out);
}

// round 2
// speedup vs baseline: 1.8827x; 1.8827x over previous
#include <cuda_runtime.h>
#include <math.h>

// Problem constants (fixed shapes for RNN_11828339933262)
#define BATCH 4
#define SEQ   2048
#define DIM   2048
#define NHEADS 32
#define HDIM  64
#define MTOT  (BATCH * SEQ) // 8192

// Scratch (device globals: allocation-free)
__device__ float g_h[(size_t)MTOT * DIM];   // input-projection output
__device__ float g_s[(size_t)MTOT * DIM];   // rnn states -> rmsnorm'd in place

// ---------------------------------------------------------------------------
// TF32 tensor-core GEMM: C[m][n] = bias[n] + sum_k A[m][k]*B[n][k]
// A: (M,K) row-major, B: (N,K) row-major. mma.sync.m16n8k8.tf32, RN conversion.
// CTA tile 128x128, BK=32, 256 threads (8 warps, 2x4), warp tile 64x32.
// ---------------------------------------------------------------------------
#define BM 128
#define BN 128
#define BK 32
#define SA 136   // BM + 8 pad: makes frag-LDS bank pattern (8*tg + gid) conflict-free

__device__ __forceinline__ unsigned f2tf32(float f) {
    unsigned u;
    asm("cvt.rna.tf32.f32 %0, %1;" : "=r"(u) : "f"(f));
    return u;
}

__device__ __forceinline__ void mma_tf32(float c[4],
    unsigned a0, unsigned a1, unsigned a2, unsigned a3,
    unsigned b0, unsigned b1)
{
    asm volatile(
        "mma.sync.aligned.m16n8k8.row.col.f32.tf32.tf32.f32 "
        "{%0,%1,%2,%3}, {%4,%5,%6,%7}, {%8,%9}, {%0,%1,%2,%3};"
        : "+f"(c[0]), "+f"(c[1]), "+f"(c[2]), "+f"(c[3])
        : "r"(a0), "r"(a1), "r"(a2), "r"(a3), "r"(b0), "r"(b1));
}

__device__ __forceinline__ void gemm_tf32_body(
    const float* __restrict__ A, const float* __restrict__ B,
    const float* __restrict__ bias, float* __restrict__ C,
    int M, int N, int K)
{
    __shared__ unsigned As[BK][SA];
    __shared__ unsigned Bs[BK][SA];

    const int tid  = threadIdx.x;
    const int lane = tid & 31;
    const int wid  = tid >> 5;
    const int cRow = blockIdx.y * BM;
    const int cCol = blockIdx.x * BN;

    const int m0 = (wid & 1) * 64;   // warp M offset
    const int n0 = (wid >> 1) * 32;  // warp N offset
    const int gid = lane >> 2;       // 0..7
    const int tg  = lane & 3;        // 0..3

    // loader: thread -> row lm (0..127), k-chunk lk (0 or 16)
    const int lm = tid >> 1;
    const int lk = (tid & 1) * 16;

    const float* Aptr = A + (size_t)(cRow + lm) * K + lk;
    const float* Bptr = B + (size_t)(cCol + lm) * K + lk;

    float acc[4][4][4];
#pragma unroll
    for (int mf = 0; mf < 4; mf++)
#pragma unroll
        for (int nf = 0; nf < 4; nf++)
#pragma unroll
            for (int i = 0; i < 4; i++) acc[mf][nf][i] = 0.f;

    for (int k0 = 0; k0 < K; k0 += BK) {
#pragma unroll
        for (int i = 0; i < 4; i++) {
            float4 va = *(const float4*)(Aptr + k0 + 4 * i);
            float4 vb = *(const float4*)(Bptr + k0 + 4 * i);
            int kk = lk + 4 * i;
            As[kk + 0][lm] = f2tf32(va.x);
            As[kk + 1][lm] = f2tf32(va.y);
            As[kk + 2][lm] = f2tf32(va.z);
            As[kk + 3][lm] = f2tf32(va.w);
            Bs[kk + 0][lm] = f2tf32(vb.x);
            Bs[kk + 1][lm] = f2tf32(vb.y);
            Bs[kk + 2][lm] = f2tf32(vb.z);
            Bs[kk + 3][lm] = f2tf32(vb.w);
        }
        __syncthreads();

#pragma unroll
        for (int ks = 0; ks < 4; ks++) {
            const int kr = 8 * ks + tg;
            unsigned a[4][4], b[4][2];
#pragma unroll
            for (int mf = 0; mf < 4; mf++) {
                int m = m0 + 16 * mf + gid;
                a[mf][0] = As[kr][m];
                a[mf][1] = As[kr][m + 8];
                a[mf][2] = As[kr + 4][m];
                a[mf][3] = As[kr + 4][m + 8];
            }
#pragma unroll
            for (int nf = 0; nf < 4; nf++) {
                int n = n0 + 8 * nf + gid;
                b[nf][0] = Bs[kr][n];
                b[nf][1] = Bs[kr + 4][n];
            }
#pragma unroll
            for (int mf = 0; mf < 4; mf++)
#pragma unroll
                for (int nf = 0; nf < 4; nf++)
                    mma_tf32(acc[mf][nf], a[mf][0], a[mf][1], a[mf][2], a[mf][3],
                             b[nf][0], b[nf][1]);
        }
        __syncthreads();
    }

    // epilogue: c0/c1 at (row, 2tg..2tg+1), c2/c3 at (row+8, ...)
#pragma unroll
    for (int mf = 0; mf < 4; mf++) {
        int row = cRow + m0 + 16 * mf + gid;
#pragma unroll
        for (int nf = 0; nf < 4; nf++) {
            int col = cCol + n0 + 8 * nf + 2 * tg;
            float b0 = 0.f, b1 = 0.f;
            if (bias) { b0 = bias[col]; b1 = bias[col + 1]; }
            float2 v0 = make_float2(acc[mf][nf][0] + b0, acc[mf][nf][1] + b1);
            float2 v1 = make_float2(acc[mf][nf][2] + b0, acc[mf][nf][3] + b1);
            *(float2*)(C + (size_t)row * N + col) = v0;
            *(float2*)(C + (size_t)(row + 8) * N + col) = v1;
        }
    }
}

__global__ __launch_bounds__(256) void gemm_in_kernel(
    const float* __restrict__ x, const float* __restrict__ w_in,
    const float* __restrict__ b_in)
{
    gemm_tf32_body(x, w_in, b_in, g_h, MTOT, DIM, DIM);
}

__global__ __launch_bounds__(256) void gemm_out_kernel(
    const float* __restrict__ w_out, float* __restrict__ out)
{
    gemm_tf32_body(g_s, w_out, nullptr, out, MTOT, DIM, DIM);
}

// ---------------------------------------------------------------------------
// RNN scan: s_t = tanh(s_{t-1} @ W + x_t). One CTA per (b,n), 128 threads:
// thread pair (2j, 2j+1) owns output j, each half does 32 MACs, shfl-reduce.
// tanh via exp2-based formula (exact saturation), no libm branches.
// ---------------------------------------------------------------------------
__global__ __launch_bounds__(128) void rnn_scan_kernel(
    const float* __restrict__ state_weight)
{
    const int b = blockIdx.x >> 5;
    const int n = blockIdx.x & 31;
    const int tid = threadIdx.x;
    const int j = tid >> 1;
    const int half = tid & 1;

    __shared__ float s_sh[2][HDIM];

    float Wc[32];
    const float* Wn = state_weight + (size_t)n * HDIM * HDIM;
#pragma unroll
    for (int k = 0; k < 32; k++)
        Wc[k] = Wn[(32 * half + k) * HDIM + j];

    if (half == 0) s_sh[0][j] = 0.f;
    __syncthreads();

    const size_t base = ((size_t)b * SEQ) * DIM + n * HDIM + j;
    float xt = g_h[base];
    int cur = 0;

    for (int t = 0; t < SEQ; t++) {
        float xn = (t + 1 < SEQ) ? g_h[base + (size_t)(t + 1) * DIM] : 0.f;

        const float4* sp = (const float4*)&s_sh[cur][32 * half];
        float a0 = 0.f, a1 = 0.f, a2 = 0.f, a3 = 0.f;
#pragma unroll
        for (int k4 = 0; k4 < 8; k4++) {
            float4 v = sp[k4];
            a0 = fmaf(v.x, Wc[4 * k4 + 0], a0);
            a1 = fmaf(v.y, Wc[4 * k4 + 1], a1);
            a2 = fmaf(v.z, Wc[4 * k4 + 2], a2);
            a3 = fmaf(v.w, Wc[4 * k4 + 3], a3);
        }
        float p = (a0 + a1) + (a2 + a3);
        p += __shfl_xor_sync(0xFFFFFFFFu, p, 1);
        float z = p + xt;
        // tanh(z) = 1 - 2/(e^{2z}+1): saturates correctly at +/-inf
        float e = __expf(2.f * z);
        float sv = 1.f - __fdividef(2.f, e + 1.f);

        if (half == 0) s_sh[cur ^ 1][j] = sv;
        else           g_s[base + (size_t)t * DIM] = sv;
        xt = xn;
        cur ^= 1;
        __syncthreads();
    }
}

// ---------------------------------------------------------------------------
// RMSNorm in place on g_s
// ---------------------------------------------------------------------------
__global__ __launch_bounds__(256) void rmsnorm_kernel(
    const float* __restrict__ norm_weight)
{
    const int row = blockIdx.x;
    float* p = g_s + (size_t)row * DIM;
    const int t = threadIdx.x;

    float4 a = ((const float4*)p)[t];
    float4 b = ((const float4*)p)[t + 256];
    float ss = a.x * a.x + a.y * a.y + a.z * a.z + a.w * a.w
             + b.x * b.x + b.y * b.y + b.z * b.z + b.w * b.w;

#pragma unroll
    for (int off = 16; off > 0; off >>= 1)
        ss += __shfl_xor_sync(0xFFFFFFFFu, ss, off);

    __shared__ float red[8];
    const int warp = t >> 5;
    const int lane = t & 31;
    if (lane == 0) red[warp] = ss;
    __syncthreads();
    if (warp == 0) {
        float v = (lane < 8) ? red[lane] : 0.f;
#pragma unroll
        for (int off = 4; off > 0; off >>= 1)
            v += __shfl_xor_sync(0xFFFFFFFFu, v, off);
        if (lane == 0) red[0] = v;
    }
    __syncthreads();
    const float scale = rsqrtf(red[0] * (1.0f / DIM) + 1e-6f);

    float4 ga = ((const float4*)norm_weight)[t];
    float4 gb = ((const float4*)norm_weight)[t + 256];
    a.x *= scale * ga.x; a.y *= scale * ga.y; a.z *= scale * ga.z; a.w *= scale * ga.w;
    b.x *= scale * gb.x; b.y *= scale * gb.y; b.z *= scale * gb.z; b.w *= scale * gb.w;
    ((float4*)p)[t]       = a;
    ((float4*)p)[t + 256] = b;
}

// ---------------------------------------------------------------------------
// Launch
// ---------------------------------------------------------------------------
extern "C" void kernel_launch(void* const* d_in, const int* in_sizes, int n_in,
                              void* d_out, int out_size)
{
    const float* x            = (const float*)d_in[0];
    const float* w_in         = (const float*)d_in[1];
    const float* b_in         = (const float*)d_in[2];
    const float* state_weight = (const float*)d_in[3];
    const float* norm_weight  = (const float*)d_in[4];
    const float* w_out        = (const float*)d_in[5];
    float* out = (float*)d_out;

    dim3 gemm_grid(DIM / BN, MTOT / BM);   // (16, 64)

    gemm_in_kernel<<<gemm_grid, 256>>>(x, w_in, b_in);
    rnn_scan_kernel<<<BATCH * NHEADS, 128>>>(state_weight);
    rmsnorm_kernel<<<MTOT, 256>>>(norm_weight);
    gemm_out_kernel<<<gemm_grid, 256>>>(w_out, out);
}

// round 4
// speedup vs baseline: 2.7206x; 1.4450x over previous
#include <cuda_runtime.h>
#include <math.h>
#include <stdint.h>

// Problem constants
#define BATCH 4
#define SEQ   2048
#define DIM   2048
#define NHEADS 32
#define HDIM  64
#define MTOT  (BATCH * SEQ) // 8192

// Scratch (device globals: allocation-free)
__device__ float g_h[(size_t)MTOT * DIM];   // input-projection output (f32)
__device__ float g_s[(size_t)MTOT * DIM];   // rnn states -> rmsnorm'd (tf32-rounded)
__device__ float g_x[(size_t)MTOT * DIM];   // x, tf32-rounded
__device__ float g_w1[(size_t)DIM * DIM];   // w_in, tf32-rounded
__device__ float g_w2[(size_t)DIM * DIM];   // w_out, tf32-rounded

// ---------------------------------------------------------------------------
// helpers
// ---------------------------------------------------------------------------
__device__ __forceinline__ unsigned f2tf32(float f) {
    unsigned u;
    asm("cvt.rna.tf32.f32 %0, %1;" : "=r"(u) : "f"(f));
    return u;
}

__device__ __forceinline__ uint32_t smem_u32(const void* p) {
    uint32_t a;
    asm("{ .reg .u64 t; cvta.to.shared.u64 t, %1; cvt.u32.u64 %0, t; }"
        : "=r"(a) : "l"(p));
    return a;
}

#define CP_ASYNC16(dst, src) \
    asm volatile("cp.async.cg.shared.global [%0], [%1], 16;" \
                 :: "r"(dst), "l"(src) : "memory")
#define CP_COMMIT() asm volatile("cp.async.commit_group;" ::: "memory")
#define CP_WAIT(n)  asm volatile("cp.async.wait_group %0;" :: "n"(n) : "memory")

__device__ __forceinline__ void mma_tf32(float c[4],
    unsigned a0, unsigned a1, unsigned a2, unsigned a3,
    unsigned b0, unsigned b1)
{
    asm volatile(
        "mma.sync.aligned.m16n8k8.row.col.f32.tf32.tf32.f32 "
        "{%0,%1,%2,%3}, {%4,%5,%6,%7}, {%8,%9}, {%0,%1,%2,%3};"
        : "+f"(c[0]), "+f"(c[1]), "+f"(c[2]), "+f"(c[3])
        : "r"(a0), "r"(a1), "r"(a2), "r"(a3), "r"(b0), "r"(b1));
}

// ---------------------------------------------------------------------------
// TF32 mma.sync GEMM, cp.async 3-stage pipeline.
// C[m][n] = bias[n] + sum_k A[m][k]*B[n][k]; A (M,K), B (N,K) row-major,
// both pre-rounded to tf32 bit patterns.
// CTA tile 128x256, BK=32, 256 threads = 8 warps (2 M x 4 N), warp tile 64x64.
// ---------------------------------------------------------------------------
#define GBM 128
#define GBN 256
#define GBK 32
#define NSTAGE 3
#define SKA 36               // BK + 4 pad -> bank = (4m+k)%32, conflict-free
#define NCHUNK (DIM / GBK)   // 64

struct Stage {
    unsigned a[GBM][SKA];    // 18432 B
    unsigned b[GBN][SKA];    // 36864 B
};

__global__ __launch_bounds__(256, 1)
void gemm_tc_kernel(const float* __restrict__ A, const float* __restrict__ B,
                    const float* __restrict__ bias, float* __restrict__ C)
{
    extern __shared__ Stage stg[];   // [NSTAGE]

    const int tid  = threadIdx.x;
    const int lane = tid & 31;
    const int wid  = tid >> 5;
    const int cRow = blockIdx.y * GBM;
    const int cCol = blockIdx.x * GBN;

    const int m0  = (wid & 1) * 64;
    const int n0  = (wid >> 1) * 64;
    const int gid = lane >> 2;   // 0..7
    const int tg  = lane & 3;    // 0..3

    float acc[4][8][4];
#pragma unroll
    for (int mf = 0; mf < 4; mf++)
#pragma unroll
        for (int nf = 0; nf < 8; nf++)
#pragma unroll
            for (int i = 0; i < 4; i++) acc[mf][nf][i] = 0.f;

    // ---- loader: chunk c into stage s (A: 4 float4/thread, B: 8) ----
    auto load_chunk = [&](int c, int s) {
        if (c < NCHUNK) {
            const long kOff = (long)c * GBK;
#pragma unroll
            for (int i = 0; i < 4; i++) {
                const int id  = tid + 256 * i;
                const int row = id >> 3;
                const int q   = id & 7;
                const float* src = A + (size_t)(cRow + row) * DIM + kOff + 4 * q;
                CP_ASYNC16(smem_u32(&stg[s].a[row][4 * q]), src);
            }
#pragma unroll
            for (int i = 0; i < 8; i++) {
                const int id  = tid + 256 * i;
                const int row = id >> 3;
                const int q   = id & 7;
                const float* src = B + (size_t)(cCol + row) * DIM + kOff + 4 * q;
                CP_ASYNC16(smem_u32(&stg[s].b[row][4 * q]), src);
            }
        }
        CP_COMMIT();   // empty groups at tail keep wait_group accounting uniform
    };

    // prologue
    for (int s = 0; s < NSTAGE; s++) load_chunk(s, s);

    for (int c = 0; c < NCHUNK; c++) {
        const int s = c % NSTAGE;
        CP_WAIT(NSTAGE - 1);
        __syncthreads();

        const unsigned(*As)[SKA] = stg[s].a;
        const unsigned(*Bs)[SKA] = stg[s].b;

#pragma unroll
        for (int ks = 0; ks < 4; ks++) {
            const int k0 = 8 * ks + tg;
            unsigned a[4][4], b[8][2];
#pragma unroll
            for (int mf = 0; mf < 4; mf++) {
                const int m = m0 + 16 * mf + gid;
                a[mf][0] = As[m][k0];
                a[mf][1] = As[m + 8][k0];
                a[mf][2] = As[m][k0 + 4];
                a[mf][3] = As[m + 8][k0 + 4];
            }
#pragma unroll
            for (int nf = 0; nf < 8; nf++) {
                const int n = n0 + 8 * nf + gid;
                b[nf][0] = Bs[n][k0];
                b[nf][1] = Bs[n][k0 + 4];
            }
#pragma unroll
            for (int mf = 0; mf < 4; mf++)
#pragma unroll
                for (int nf = 0; nf < 8; nf++)
                    mma_tf32(acc[mf][nf], a[mf][0], a[mf][1], a[mf][2], a[mf][3],
                             b[nf][0], b[nf][1]);
        }
        __syncthreads();
        load_chunk(c + NSTAGE, s);
    }

    // epilogue
#pragma unroll
    for (int mf = 0; mf < 4; mf++) {
        const int row = cRow + m0 + 16 * mf + gid;
#pragma unroll
        for (int nf = 0; nf < 8; nf++) {
            const int col = cCol + n0 + 8 * nf + 2 * tg;
            float b0 = 0.f, b1 = 0.f;
            if (bias) { b0 = bias[col]; b1 = bias[col + 1]; }
            float2 v0 = make_float2(acc[mf][nf][0] + b0, acc[mf][nf][1] + b1);
            float2 v1 = make_float2(acc[mf][nf][2] + b0, acc[mf][nf][3] + b1);
            *(float2*)(C + (size_t)row * DIM + col) = v0;
            *(float2*)(C + (size_t)(row + 8) * DIM + col) = v1;
        }
    }
}

// ---------------------------------------------------------------------------
// tf32 pre-round: out[i] = rna_tf32(in[i])
// ---------------------------------------------------------------------------
__global__ __launch_bounds__(256) void cvt_tf32_kernel(
    const float* __restrict__ in, float* __restrict__ out)
{
    const size_t i = (size_t)blockIdx.x * 256 + threadIdx.x;
    float4 v = ((const float4*)in)[i];
    v.x = __uint_as_float(f2tf32(v.x));
    v.y = __uint_as_float(f2tf32(v.y));
    v.z = __uint_as_float(f2tf32(v.z));
    v.w = __uint_as_float(f2tf32(v.w));
    ((float4*)out)[i] = v;
}

// ---------------------------------------------------------------------------
// RNN scan: s_t = tanh(s_{t-1} @ W + x_t). One CTA per (b,n), 128 threads:
// pair (2j,2j+1) owns output j (32 MACs each + shfl reduce).
// Depth-4 input prefetch hides g_h load latency.
// ---------------------------------------------------------------------------
__global__ __launch_bounds__(128) void rnn_scan_kernel(
    const float* __restrict__ state_weight)
{
    const int b = blockIdx.x >> 5;
    const int n = blockIdx.x & 31;
    const int tid = threadIdx.x;
    const int j = tid >> 1;
    const int half = tid & 1;

    __shared__ float s_sh[2][HDIM];

    float Wc[32];
    const float* Wn = state_weight + (size_t)n * HDIM * HDIM;
#pragma unroll
    for (int k = 0; k < 32; k++)
        Wc[k] = Wn[(32 * half + k) * HDIM + j];

    if (half == 0) s_sh[0][j] = 0.f;
    __syncthreads();

    const size_t base = ((size_t)b * SEQ) * DIM + n * HDIM + j;
    const float* gin = g_h + base;
    float* gout = g_s + base;

    float pf0 = __ldg(gin + 0 * DIM);
    float pf1 = __ldg(gin + 1 * DIM);
    float pf2 = __ldg(gin + 2 * DIM);
    float pf3 = __ldg(gin + 3 * DIM);
    const float* gpf = gin + 4 * DIM;

    int cur = 0;

#define SCAN_STEP(XT, T)                                                     \
    do {                                                                     \
        const float4* sp = (const float4*)&s_sh[cur][32 * half];             \
        float a0 = 0.f, a1 = 0.f, a2 = 0.f, a3 = 0.f;                        \
        _Pragma("unroll")                                                    \
        for (int k4 = 0; k4 < 8; k4++) {                                     \
            float4 v = sp[k4];                                               \
            a0 = fmaf(v.x, Wc[4 * k4 + 0], a0);                              \
            a1 = fmaf(v.y, Wc[4 * k4 + 1], a1);                              \
            a2 = fmaf(v.z, Wc[4 * k4 + 2], a2);                              \
            a3 = fmaf(v.w, Wc[4 * k4 + 3], a3);                              \
        }                                                                    \
        float p = (a0 + a1) + (a2 + a3);                                     \
        p += __shfl_xor_sync(0xFFFFFFFFu, p, 1);                             \
        float z = p + (XT);                                                  \
        float e = __expf(2.f * z);                                           \
        float sv = 1.f - __fdividef(2.f, e + 1.f);                           \
        if (half == 0) s_sh[cur ^ 1][j] = sv;                                \
        else           gout[(size_t)(T) * DIM] = sv;                         \
        cur ^= 1;                                                            \
        __syncthreads();                                                     \
    } while (0)

    for (int t = 0; t < SEQ; t += 4) {
        SCAN_STEP(pf0, t + 0);
        pf0 = (t + 4 < SEQ) ? __ldg(gpf + 0 * DIM) : 0.f;
        SCAN_STEP(pf1, t + 1);
        pf1 = (t + 5 < SEQ) ? __ldg(gpf + 1 * DIM) : 0.f;
        SCAN_STEP(pf2, t + 2);
        pf2 = (t + 6 < SEQ) ? __ldg(gpf + 2 * DIM) : 0.f;
        SCAN_STEP(pf3, t + 3);
        pf3 = (t + 7 < SEQ) ? __ldg(gpf + 3 * DIM) : 0.f;
        gpf += 4 * DIM;
    }
#undef SCAN_STEP
}

// ---------------------------------------------------------------------------
// RMSNorm in place on g_s; output pre-rounded to tf32 (A operand of gemm_out)
// ---------------------------------------------------------------------------
__global__ __launch_bounds__(256) void rmsnorm_kernel(
    const float* __restrict__ norm_weight)
{
    const int row = blockIdx.x;
    float* p = g_s + (size_t)row * DIM;
    const int t = threadIdx.x;

    float4 a = ((const float4*)p)[t];
    float4 b = ((const float4*)p)[t + 256];
    float ss = a.x * a.x + a.y * a.y + a.z * a.z + a.w * a.w
             + b.x * b.x + b.y * b.y + b.z * b.z + b.w * b.w;

#pragma unroll
    for (int off = 16; off > 0; off >>= 1)
        ss += __shfl_xor_sync(0xFFFFFFFFu, ss, off);

    __shared__ float red[8];
    const int warp = t >> 5;
    const int lane = t & 31;
    if (lane == 0) red[warp] = ss;
    __syncthreads();
    if (warp == 0) {
        float v = (lane < 8) ? red[lane] : 0.f;
#pragma unroll
        for (int off = 4; off > 0; off >>= 1)
            v += __shfl_xor_sync(0xFFFFFFFFu, v, off);
        if (lane == 0) red[0] = v;
    }
    __syncthreads();
    const float scale = rsqrtf(red[0] * (1.0f / DIM) + 1e-6f);

    float4 ga = ((const float4*)norm_weight)[t];
    float4 gb = ((const float4*)norm_weight)[t + 256];
    a.x = __uint_as_float(f2tf32(a.x * scale * ga.x));
    a.y = __uint_as_float(f2tf32(a.y * scale * ga.y));
    a.z = __uint_as_float(f2tf32(a.z * scale * ga.z));
    a.w = __uint_as_float(f2tf32(a.w * scale * ga.w));
    b.x = __uint_as_float(f2tf32(b.x * scale * gb.x));
    b.y = __uint_as_float(f2tf32(b.y * scale * gb.y));
    b.z = __uint_as_float(f2tf32(b.z * scale * gb.z));
    b.w = __uint_as_float(f2tf32(b.w * scale * gb.w));
    ((float4*)p)[t]       = a;
    ((float4*)p)[t + 256] = b;
}

// ---------------------------------------------------------------------------
// Launch
// ---------------------------------------------------------------------------
extern "C" void kernel_launch(void* const* d_in, const int* in_sizes, int n_in,
                              void* d_out, int out_size)
{
    const float* x            = (const float*)d_in[0];
    const float* w_in         = (const float*)d_in[1];
    const float* b_in         = (const float*)d_in[2];
    const float* state_weight = (const float*)d_in[3];
    const float* norm_weight  = (const float*)d_in[4];
    const float* w_out        = (const float*)d_in[5];
    float* out = (float*)d_out;

    float *gx, *gw1, *gw2, *gh, *gs;
    cudaGetSymbolAddress((void**)&gx,  g_x);
    cudaGetSymbolAddress((void**)&gw1, g_w1);
    cudaGetSymbolAddress((void**)&gw2, g_w2);
    cudaGetSymbolAddress((void**)&gh,  g_h);
    cudaGetSymbolAddress((void**)&gs,  g_s);

    const int SMEM_TOTAL = (int)sizeof(Stage) * NSTAGE;   // 165888
    cudaFuncSetAttribute(gemm_tc_kernel,
                         cudaFuncAttributeMaxDynamicSharedMemorySize, SMEM_TOTAL);

    // pre-round operands to tf32 so cp.async byte copies are exact
    cvt_tf32_kernel<<<(MTOT * DIM) / 1024, 256>>>(x, gx);
    cvt_tf32_kernel<<<(DIM * DIM) / 1024, 256>>>(w_in, gw1);
    cvt_tf32_kernel<<<(DIM * DIM) / 1024, 256>>>(w_out, gw2);

    dim3 ggrid(DIM / GBN, MTOT / GBM);   // (8, 64)

    gemm_tc_kernel<<<ggrid, 256, SMEM_TOTAL>>>(gx, gw1, b_in, gh);
    rnn_scan_kernel<<<BATCH * NHEADS, 128>>>(state_weight);
    rmsnorm_kernel<<<MTOT, 256>>>(norm_weight);
    gemm_tc_kernel<<<ggrid, 256, SMEM_TOTAL>>>(gs, gw2, nullptr, out);
}

// round 5
// speedup vs baseline: 3.1556x; 1.1599x over previous
#include <cuda_runtime.h>
#include <math.h>
#include <stdint.h>

// Problem constants
#define BATCH 4
#define SEQ   2048
#define DIM   2048
#define NHEADS 32
#define HDIM  64
#define MTOT  (BATCH * SEQ) // 8192

// Scratch (device globals: allocation-free)
__device__ float g_h[(size_t)MTOT * DIM];   // input-projection output (f32)
__device__ float g_s[(size_t)MTOT * DIM];   // rnn states, tf32-rounded
__device__ float g_x[(size_t)MTOT * DIM];   // x, tf32-rounded
__device__ float g_w1[(size_t)DIM * DIM];   // w_in, tf32-rounded
__device__ float g_w2[(size_t)DIM * DIM];   // w_out * norm_weight, tf32-rounded
__device__ float g_scale[MTOT];             // per-row rmsnorm scale

// ---------------------------------------------------------------------------
// helpers
// ---------------------------------------------------------------------------
__device__ __forceinline__ unsigned f2tf32(float f) {
    unsigned u;
    asm("cvt.rna.tf32.f32 %0, %1;" : "=r"(u) : "f"(f));
    return u;
}

__device__ __forceinline__ uint32_t smem_u32(const void* p) {
    uint32_t a;
    asm("{ .reg .u64 t; cvta.to.shared.u64 t, %1; cvt.u32.u64 %0, t; }"
        : "=r"(a) : "l"(p));
    return a;
}

#define CP_ASYNC16(dst, src) \
    asm volatile("cp.async.cg.shared.global [%0], [%1], 16;" \
                 :: "r"(dst), "l"(src) : "memory")
#define CP_COMMIT() asm volatile("cp.async.commit_group;" ::: "memory")
#define CP_WAIT(n)  asm volatile("cp.async.wait_group %0;" :: "n"(n) : "memory")

__device__ __forceinline__ void mma_tf32(float c[4],
    unsigned a0, unsigned a1, unsigned a2, unsigned a3,
    unsigned b0, unsigned b1)
{
    asm volatile(
        "mma.sync.aligned.m16n8k8.row.col.f32.tf32.tf32.f32 "
        "{%0,%1,%2,%3}, {%4,%5,%6,%7}, {%8,%9}, {%0,%1,%2,%3};"
        : "+f"(c[0]), "+f"(c[1]), "+f"(c[2]), "+f"(c[3])
        : "r"(a0), "r"(a1), "r"(a2), "r"(a3), "r"(b0), "r"(b1));
}

// ---------------------------------------------------------------------------
// TF32 mma.sync GEMM, cp.async 3-stage pipeline, ONE sync per chunk,
// sized for 2 CTAs/SM (smem 110.6KB/CTA, regs<=128).
// C[m][n] = (bias[n] +) rowScale[m] * sum_k A[m][k]*B[n][k]
// A (M,K), B (N,K) row-major, pre-rounded tf32 bit patterns.
// CTA tile 128x128, BK=32, 256 thr = 8 warps (2M x 4N), warp tile 64x32.
// ---------------------------------------------------------------------------
#define GBM 128
#define GBN 128
#define GBK 32
#define NSTAGE 3
#define SKA 36               // BK + 4 pad -> LDS bank = (4*gid+tg)%32, conflict-free
#define NCHUNK (DIM / GBK)   // 64

struct Stage {
    unsigned a[GBM][SKA];
    unsigned b[GBN][SKA];
};

__global__ __launch_bounds__(256, 2)
void gemm_tc_kernel(const float* __restrict__ A, const float* __restrict__ B,
                    const float* __restrict__ bias, float* __restrict__ C,
                    const float* __restrict__ rowScale)
{
    extern __shared__ Stage stg[];   // [NSTAGE]

    const int tid  = threadIdx.x;
    const int lane = tid & 31;
    const int wid  = tid >> 5;
    const int cRow = blockIdx.y * GBM;
    const int cCol = blockIdx.x * GBN;

    const int m0  = (wid & 1) * 64;
    const int n0  = (wid >> 1) * 32;
    const int gid = lane >> 2;   // 0..7
    const int tg  = lane & 3;    // 0..3

    float acc[4][4][4];
#pragma unroll
    for (int mf = 0; mf < 4; mf++)
#pragma unroll
        for (int nf = 0; nf < 4; nf++)
#pragma unroll
            for (int i = 0; i < 4; i++) acc[mf][nf][i] = 0.f;

    // loader: 4 float4/thread for A, 4 for B (128 rows x 8 slots each)
    const int lrow = tid >> 3;        // base row 0..31 step +32
    const int lq   = tid & 7;         // float4 slot in row
    auto load_chunk = [&](int c, int s) {
        if (c < NCHUNK) {
            const long kOff = (long)c * GBK + 4 * lq;
#pragma unroll
            for (int i = 0; i < 4; i++) {
                const int row = lrow + 32 * i;
                CP_ASYNC16(smem_u32(&stg[s].a[row][4 * lq]),
                           A + (size_t)(cRow + row) * DIM + kOff);
            }
#pragma unroll
            for (int i = 0; i < 4; i++) {
                const int row = lrow + 32 * i;
                CP_ASYNC16(smem_u32(&stg[s].b[row][4 * lq]),
                           B + (size_t)(cCol + row) * DIM + kOff);
            }
        }
        CP_COMMIT();
    };

    // prologue: chunks 0 .. NSTAGE-2
    for (int s = 0; s < NSTAGE - 1; s++) load_chunk(s, s);

    for (int c = 0; c < NCHUNK; c++) {
        const int s = c % NSTAGE;
        CP_WAIT(NSTAGE - 2);      // chunk c's data resident
        __syncthreads();          // also: everyone done computing chunk c-1
        load_chunk(c + NSTAGE - 1, (c + NSTAGE - 1) % NSTAGE);

        const unsigned(*As)[SKA] = stg[s].a;
        const unsigned(*Bs)[SKA] = stg[s].b;

#pragma unroll
        for (int ks = 0; ks < 4; ks++) {
            const int k0 = 8 * ks + tg;
            unsigned a[4][4], b[4][2];
#pragma unroll
            for (int mf = 0; mf < 4; mf++) {
                const int m = m0 + 16 * mf + gid;
                a[mf][0] = As[m][k0];
                a[mf][1] = As[m + 8][k0];
                a[mf][2] = As[m][k0 + 4];
                a[mf][3] = As[m + 8][k0 + 4];
            }
#pragma unroll
            for (int nf = 0; nf < 4; nf++) {
                const int n = n0 + 8 * nf + gid;
                b[nf][0] = Bs[n][k0];
                b[nf][1] = Bs[n][k0 + 4];
            }
#pragma unroll
            for (int mf = 0; mf < 4; mf++)
#pragma unroll
                for (int nf = 0; nf < 4; nf++)
                    mma_tf32(acc[mf][nf], a[mf][0], a[mf][1], a[mf][2], a[mf][3],
                             b[nf][0], b[nf][1]);
        }
    }

    // epilogue
#pragma unroll
    for (int mf = 0; mf < 4; mf++) {
        const int row = cRow + m0 + 16 * mf + gid;
        const float rs0 = rowScale ? rowScale[row] : 1.f;
        const float rs1 = rowScale ? rowScale[row + 8] : 1.f;
#pragma unroll
        for (int nf = 0; nf < 4; nf++) {
            const int col = cCol + n0 + 8 * nf + 2 * tg;
            float b0 = 0.f, b1 = 0.f;
            if (bias) { b0 = bias[col]; b1 = bias[col + 1]; }
            float2 v0 = make_float2(acc[mf][nf][0] * rs0 + b0, acc[mf][nf][1] * rs0 + b1);
            float2 v1 = make_float2(acc[mf][nf][2] * rs1 + b0, acc[mf][nf][3] * rs1 + b1);
            *(float2*)(C + (size_t)row * DIM + col) = v0;
            *(float2*)(C + (size_t)(row + 8) * DIM + col) = v1;
        }
    }
}

// ---------------------------------------------------------------------------
// tf32 pre-round; optional per-column scale (folds norm_weight into w_out)
// ---------------------------------------------------------------------------
__global__ __launch_bounds__(256) void cvt_tf32_kernel(
    const float* __restrict__ in, float* __restrict__ out)
{
    const size_t i = (size_t)blockIdx.x * 256 + threadIdx.x;
    float4 v = ((const float4*)in)[i];
    v.x = __uint_as_float(f2tf32(v.x));
    v.y = __uint_as_float(f2tf32(v.y));
    v.z = __uint_as_float(f2tf32(v.z));
    v.w = __uint_as_float(f2tf32(v.w));
    ((float4*)out)[i] = v;
}

__global__ __launch_bounds__(256) void cvt_tf32_colscale_kernel(
    const float* __restrict__ in, const float* __restrict__ colw,
    float* __restrict__ out)
{
    const size_t i = (size_t)blockIdx.x * 256 + threadIdx.x;
    const int c4 = (int)((i * 4) & (DIM - 1));
    float4 v = ((const float4*)in)[i];
    const float4 g = *(const float4*)(colw + c4);
    v.x = __uint_as_float(f2tf32(v.x * g.x));
    v.y = __uint_as_float(f2tf32(v.y * g.y));
    v.z = __uint_as_float(f2tf32(v.z * g.z));
    v.w = __uint_as_float(f2tf32(v.w * g.w));
    ((float4*)out)[i] = v;
}

// ---------------------------------------------------------------------------
// RNN scan: pair-split (128 thr), depth-8 prefetch, tf32-rounded stores.
// ---------------------------------------------------------------------------
__global__ __launch_bounds__(128) void rnn_scan_kernel(
    const float* __restrict__ state_weight)
{
    const int b = blockIdx.x >> 5;
    const int n = blockIdx.x & 31;
    const int tid = threadIdx.x;
    const int j = tid >> 1;
    const int half = tid & 1;

    __shared__ float s_sh[2][HDIM];

    float Wc[32];
    const float* Wn = state_weight + (size_t)n * HDIM * HDIM;
#pragma unroll
    for (int k = 0; k < 32; k++)
        Wc[k] = Wn[(32 * half + k) * HDIM + j];

    if (half == 0) s_sh[0][j] = 0.f;
    __syncthreads();

    const size_t base = ((size_t)b * SEQ) * DIM + n * HDIM + j;
    const float* gin = g_h + base;
    float* gout = g_s + base;

    float pf[8];
#pragma unroll
    for (int u = 0; u < 8; u++) pf[u] = __ldg(gin + (size_t)u * DIM);
    const float* gpf = gin + 8 * DIM;

    int cur = 0;

#define SCAN_STEP(XT, T)                                                     \
    do {                                                                     \
        const float4* sp = (const float4*)&s_sh[cur][32 * half];             \
        float a0 = 0.f, a1 = 0.f, a2 = 0.f, a3 = 0.f;                        \
        _Pragma("unroll")                                                    \
        for (int k4 = 0; k4 < 8; k4++) {                                     \
            float4 v = sp[k4];                                               \
            a0 = fmaf(v.x, Wc[4 * k4 + 0], a0);                              \
            a1 = fmaf(v.y, Wc[4 * k4 + 1], a1);                              \
            a2 = fmaf(v.z, Wc[4 * k4 + 2], a2);                              \
            a3 = fmaf(v.w, Wc[4 * k4 + 3], a3);                              \
        }                                                                    \
        float p = (a0 + a1) + (a2 + a3);                                     \
        p += __shfl_xor_sync(0xFFFFFFFFu, p, 1);                             \
        float z = p + (XT);                                                  \
        float e = __expf(2.f * z);                                           \
        float sv = 1.f - __fdividef(2.f, e + 1.f);                           \
        if (half == 0) s_sh[cur ^ 1][j] = sv;                                \
        else           gout[(size_t)(T) * DIM] = __uint_as_float(f2tf32(sv));\
        cur ^= 1;                                                            \
        __syncthreads();                                                     \
    } while (0)

    for (int t = 0; t < SEQ; t += 8) {
#pragma unroll
        for (int u = 0; u < 8; u++) {
            SCAN_STEP(pf[u], t + u);
            pf[u] = (t + 8 + u < SEQ) ? __ldg(gpf + (size_t)u * DIM) : 0.f;
        }
        gpf += 8 * DIM;
    }
#undef SCAN_STEP
}

// ---------------------------------------------------------------------------
// Row scale: g_scale[row] = rsqrt(mean(g_s[row]^2) + eps). Read-only pass.
// ---------------------------------------------------------------------------
__global__ __launch_bounds__(256) void row_scale_kernel()
{
    const int row = blockIdx.x;
    const float* p = g_s + (size_t)row * DIM;
    const int t = threadIdx.x;

    float4 a = ((const float4*)p)[t];
    float4 b = ((const float4*)p)[t + 256];
    float ss = a.x * a.x + a.y * a.y + a.z * a.z + a.w * a.w
             + b.x * b.x + b.y * b.y + b.z * b.z + b.w * b.w;

#pragma unroll
    for (int off = 16; off > 0; off >>= 1)
        ss += __shfl_xor_sync(0xFFFFFFFFu, ss, off);

    __shared__ float red[8];
    const int warp = t >> 5;
    const int lane = t & 31;
    if (lane == 0) red[warp] = ss;
    __syncthreads();
    if (warp == 0) {
        float v = (lane < 8) ? red[lane] : 0.f;
#pragma unroll
        for (int off = 4; off > 0; off >>= 1)
            v += __shfl_xor_sync(0xFFFFFFFFu, v, off);
        if (lane == 0) g_scale[row] = rsqrtf(v * (1.0f / DIM) + 1e-6f);
    }
}

// ---------------------------------------------------------------------------
// Launch
// ---------------------------------------------------------------------------
extern "C" void kernel_launch(void* const* d_in, const int* in_sizes, int n_in,
                              void* d_out, int out_size)
{
    const float* x            = (const float*)d_in[0];
    const float* w_in         = (const float*)d_in[1];
    const float* b_in         = (const float*)d_in[2];
    const float* state_weight = (const float*)d_in[3];
    const float* norm_weight  = (const float*)d_in[4];
    const float* w_out        = (const float*)d_in[5];
    float* out = (float*)d_out;

    float *gx, *gw1, *gw2, *gh, *gs, *gscale;
    cudaGetSymbolAddress((void**)&gx,  g_x);
    cudaGetSymbolAddress((void**)&gw1, g_w1);
    cudaGetSymbolAddress((void**)&gw2, g_w2);
    cudaGetSymbolAddress((void**)&gh,  g_h);
    cudaGetSymbolAddress((void**)&gs,  g_s);
    cudaGetSymbolAddress((void**)&gscale, g_scale);

    const int SMEM_TOTAL = (int)sizeof(Stage) * NSTAGE;   // 110592
    cudaFuncSetAttribute(gemm_tc_kernel,
                         cudaFuncAttributeMaxDynamicSharedMemorySize, SMEM_TOTAL);

    // pre-round operands to tf32 (norm_weight folded into w_out)
    cvt_tf32_kernel<<<(MTOT * DIM) / 1024, 256>>>(x, gx);
    cvt_tf32_kernel<<<(DIM * DIM) / 1024, 256>>>(w_in, gw1);
    cvt_tf32_colscale_kernel<<<(DIM * DIM) / 1024, 256>>>(w_out, norm_weight, gw2);

    dim3 ggrid(DIM / GBN, MTOT / GBM);   // (16, 64)

    gemm_tc_kernel<<<ggrid, 256, SMEM_TOTAL>>>(gx, gw1, b_in, gh, nullptr);
    rnn_scan_kernel<<<BATCH * NHEADS, 128>>>(state_weight);
    row_scale_kernel<<<MTOT, 256>>>();
    gemm_tc_kernel<<<ggrid, 256, SMEM_TOTAL>>>(gs, gw2, nullptr, out, gscale);
}

// round 6
// speedup vs baseline: 3.4441x; 1.0914x over previous
#include <cuda_runtime.h>
#include <cuda_fp16.h>
#include <math.h>
#include <stdint.h>

// Problem constants
#define BATCH 4
#define SEQ   2048
#define DIM   2048
#define NHEADS 32
#define HDIM  64
#define MTOT  (BATCH * SEQ) // 8192

// Scratch (device globals: allocation-free)
__device__ float  g_h[(size_t)MTOT * DIM];   // input-projection output (f32)
__device__ __half g_s[(size_t)MTOT * DIM];   // rnn states (fp16)
__device__ __half g_x[(size_t)MTOT * DIM];   // x (fp16)
__device__ __half g_w1[(size_t)DIM * DIM];   // w_in (fp16)
__device__ __half g_w2[(size_t)DIM * DIM];   // w_out * norm_weight (fp16)
__device__ float  g_scale[MTOT];             // per-row rmsnorm scale

// ---------------------------------------------------------------------------
// helpers
// ---------------------------------------------------------------------------
__device__ __forceinline__ uint32_t smem_u32(const void* p) {
    uint32_t a;
    asm("{ .reg .u64 t; cvta.to.shared.u64 t, %1; cvt.u32.u64 %0, t; }"
        : "=r"(a) : "l"(p));
    return a;
}

#define CP_ASYNC16(dst, src) \
    asm volatile("cp.async.cg.shared.global [%0], [%1], 16;" \
                 :: "r"(dst), "l"(src) : "memory")
#define CP_COMMIT() asm volatile("cp.async.commit_group;" ::: "memory")
#define CP_WAIT(n)  asm volatile("cp.async.wait_group %0;" :: "n"(n) : "memory")

__device__ __forceinline__ void mma_f16(float c[4],
    unsigned a0, unsigned a1, unsigned a2, unsigned a3,
    unsigned b0, unsigned b1)
{
    asm volatile(
        "mma.sync.aligned.m16n8k16.row.col.f32.f16.f16.f32 "
        "{%0,%1,%2,%3}, {%4,%5,%6,%7}, {%8,%9}, {%0,%1,%2,%3};"
        : "+f"(c[0]), "+f"(c[1]), "+f"(c[2]), "+f"(c[3])
        : "r"(a0), "r"(a1), "r"(a2), "r"(a3), "r"(b0), "r"(b1));
}

// ---------------------------------------------------------------------------
// FP16 mma.sync GEMM (fp32 accumulate), cp.async 3-stage, 1 sync/chunk,
// 2 CTAs/SM. C[m][n] = (bias[n] +) rowScale[m] * sum_k A[m][k]*B[n][k]
// A (M,K), B (N,K) row-major fp16. CTA tile 128x128, BK=32 (2 k16-steps),
// 256 thr = 8 warps (2M x 4N), warp tile 64x32.
// ---------------------------------------------------------------------------
#define GBM 128
#define GBN 128
#define GBK 32
#define NSTAGE 3
#define SKH 40               // 32 + 8 halfs pad -> conflict-free frag LDS
#define NCHUNK (DIM / GBK)   // 64

struct Stage {
    __half a[GBM][SKH];      // 10240 B
    __half b[GBN][SKH];      // 10240 B
};

__global__ __launch_bounds__(256, 2)
void gemm_h_kernel(const __half* __restrict__ A, const __half* __restrict__ B,
                   const float* __restrict__ bias, float* __restrict__ C,
                   const float* __restrict__ rowScale)
{
    extern __shared__ Stage stg[];   // [NSTAGE]

    const int tid  = threadIdx.x;
    const int lane = tid & 31;
    const int wid  = tid >> 5;
    const int cRow = blockIdx.y * GBM;
    const int cCol = blockIdx.x * GBN;

    const int m0  = (wid & 1) * 64;
    const int n0  = (wid >> 1) * 32;
    const int gid = lane >> 2;   // 0..7
    const int tg  = lane & 3;    // 0..3

    float acc[4][4][4];
#pragma unroll
    for (int mf = 0; mf < 4; mf++)
#pragma unroll
        for (int nf = 0; nf < 4; nf++)
#pragma unroll
            for (int i = 0; i < 4; i++) acc[mf][nf][i] = 0.f;

    // loader: row = tid>>2 (+64), slot = tid&3 (8 halfs = 16B per cp)
    const int lrow  = tid >> 2;
    const int lslot = tid & 3;
    auto load_chunk = [&](int c, int s) {
        if (c < NCHUNK) {
            const long kOff = (long)c * GBK + 8 * lslot;
#pragma unroll
            for (int i = 0; i < 2; i++) {
                const int row = lrow + 64 * i;
                CP_ASYNC16(smem_u32(&stg[s].a[row][8 * lslot]),
                           A + (size_t)(cRow + row) * DIM + kOff);
                CP_ASYNC16(smem_u32(&stg[s].b[row][8 * lslot]),
                           B + (size_t)(cCol + row) * DIM + kOff);
            }
        }
        CP_COMMIT();
    };

    for (int s = 0; s < NSTAGE - 1; s++) load_chunk(s, s);

    for (int c = 0; c < NCHUNK; c++) {
        const int s = c % NSTAGE;
        CP_WAIT(NSTAGE - 2);
        __syncthreads();
        load_chunk(c + NSTAGE - 1, (c + NSTAGE - 1) % NSTAGE);

        const __half(*As)[SKH] = stg[s].a;
        const __half(*Bs)[SKH] = stg[s].b;

#pragma unroll
        for (int ks = 0; ks < 2; ks++) {       // two k16 steps per chunk
            const int kb = 16 * ks + 2 * tg;   // even -> 4B aligned
            unsigned a[4][4], b[4][2];
#pragma unroll
            for (int mf = 0; mf < 4; mf++) {
                const int m = m0 + 16 * mf + gid;
                a[mf][0] = *(const unsigned*)&As[m][kb];
                a[mf][1] = *(const unsigned*)&As[m + 8][kb];
                a[mf][2] = *(const unsigned*)&As[m][kb + 8];
                a[mf][3] = *(const unsigned*)&As[m + 8][kb + 8];
            }
#pragma unroll
            for (int nf = 0; nf < 4; nf++) {
                const int n = n0 + 8 * nf + gid;
                b[nf][0] = *(const unsigned*)&Bs[n][kb];
                b[nf][1] = *(const unsigned*)&Bs[n][kb + 8];
            }
#pragma unroll
            for (int mf = 0; mf < 4; mf++)
#pragma unroll
                for (int nf = 0; nf < 4; nf++)
                    mma_f16(acc[mf][nf], a[mf][0], a[mf][1], a[mf][2], a[mf][3],
                            b[nf][0], b[nf][1]);
        }
    }

    // epilogue: c0/c1 at (row, 2tg..), c2/c3 at (row+8, ..)
#pragma unroll
    for (int mf = 0; mf < 4; mf++) {
        const int row = cRow + m0 + 16 * mf + gid;
        const float rs0 = rowScale ? rowScale[row] : 1.f;
        const float rs1 = rowScale ? rowScale[row + 8] : 1.f;
#pragma unroll
        for (int nf = 0; nf < 4; nf++) {
            const int col = cCol + n0 + 8 * nf + 2 * tg;
            float b0 = 0.f, b1 = 0.f;
            if (bias) { b0 = bias[col]; b1 = bias[col + 1]; }
            float2 v0 = make_float2(acc[mf][nf][0] * rs0 + b0, acc[mf][nf][1] * rs0 + b1);
            float2 v1 = make_float2(acc[mf][nf][2] * rs1 + b0, acc[mf][nf][3] * rs1 + b1);
            *(float2*)(C + (size_t)row * DIM + col) = v0;
            *(float2*)(C + (size_t)(row + 8) * DIM + col) = v1;
        }
    }
}

// ---------------------------------------------------------------------------
// f32 -> fp16 conversions (8 elems/thread); colscale folds norm_weight
// ---------------------------------------------------------------------------
__global__ __launch_bounds__(256) void cvt_h_kernel(
    const float* __restrict__ in, __half* __restrict__ out)
{
    const size_t i = ((size_t)blockIdx.x * 256 + threadIdx.x) * 8;
    const float4 v0 = *(const float4*)(in + i);
    const float4 v1 = *(const float4*)(in + i + 4);
    __half2 h[4];
    h[0] = __floats2half2_rn(v0.x, v0.y);
    h[1] = __floats2half2_rn(v0.z, v0.w);
    h[2] = __floats2half2_rn(v1.x, v1.y);
    h[3] = __floats2half2_rn(v1.z, v1.w);
    *(uint4*)(out + i) = *(const uint4*)h;
}

__global__ __launch_bounds__(256) void cvt_h_colscale_kernel(
    const float* __restrict__ in, const float* __restrict__ colw,
    __half* __restrict__ out)
{
    const size_t i = ((size_t)blockIdx.x * 256 + threadIdx.x) * 8;
    const int c = (int)(i & (DIM - 1));
    const float4 v0 = *(const float4*)(in + i);
    const float4 v1 = *(const float4*)(in + i + 4);
    const float4 g0 = *(const float4*)(colw + c);
    const float4 g1 = *(const float4*)(colw + c + 4);
    __half2 h[4];
    h[0] = __floats2half2_rn(v0.x * g0.x, v0.y * g0.y);
    h[1] = __floats2half2_rn(v0.z * g0.z, v0.w * g0.w);
    h[2] = __floats2half2_rn(v1.x * g1.x, v1.y * g1.y);
    h[3] = __floats2half2_rn(v1.z * g1.z, v1.w * g1.w);
    *(uint4*)(out + i) = *(const uint4*)h;
}

// ---------------------------------------------------------------------------
// RNN scan: quad-split. 256 threads; group of 4 threads owns output j=tid>>2,
// each does 16 MACs; butterfly shfl (xor1, xor2) reduces. q0 writes smem
// state, q1 writes fp16 state to gmem. Depth-8 input prefetch.
// ---------------------------------------------------------------------------
__global__ __launch_bounds__(256) void rnn_scan_kernel(
    const float* __restrict__ state_weight)
{
    const int b = blockIdx.x >> 5;
    const int n = blockIdx.x & 31;
    const int tid = threadIdx.x;
    const int j = tid >> 2;
    const int q = tid & 3;

    __shared__ float s_sh[2][HDIM];

    float Wc[16];
    const float* Wn = state_weight + (size_t)n * HDIM * HDIM;
#pragma unroll
    for (int k = 0; k < 16; k++)
        Wc[k] = Wn[(16 * q + k) * HDIM + j];

    if (q == 0) s_sh[0][j] = 0.f;
    __syncthreads();

    const size_t base = ((size_t)b * SEQ) * DIM + n * HDIM + j;
    const float* gin = g_h + base;
    __half* gout = g_s + base;

    float pf[8];
#pragma unroll
    for (int u = 0; u < 8; u++) pf[u] = __ldg(gin + (size_t)u * DIM);
    const float* gpf = gin + 8 * DIM;

    int cur = 0;

#define SCAN_STEP(XT, T)                                                     \
    do {                                                                     \
        const float4* sp = (const float4*)&s_sh[cur][16 * q];                \
        float a0 = 0.f, a1 = 0.f, a2 = 0.f, a3 = 0.f;                        \
        _Pragma("unroll")                                                    \
        for (int k4 = 0; k4 < 4; k4++) {                                     \
            float4 v = sp[k4];                                               \
            a0 = fmaf(v.x, Wc[4 * k4 + 0], a0);                              \
            a1 = fmaf(v.y, Wc[4 * k4 + 1], a1);                              \
            a2 = fmaf(v.z, Wc[4 * k4 + 2], a2);                              \
            a3 = fmaf(v.w, Wc[4 * k4 + 3], a3);                              \
        }                                                                    \
        float p = (a0 + a1) + (a2 + a3);                                     \
        p += __shfl_xor_sync(0xFFFFFFFFu, p, 1);                             \
        p += __shfl_xor_sync(0xFFFFFFFFu, p, 2);                             \
        float z = p + (XT);                                                  \
        float e = __expf(2.f * z);                                           \
        float sv = 1.f - __fdividef(2.f, e + 1.f);                           \
        if (q == 0) s_sh[cur ^ 1][j] = sv;                                   \
        if (q == 1) gout[(size_t)(T) * DIM] = __float2half_rn(sv);           \
        cur ^= 1;                                                            \
        __syncthreads();                                                     \
    } while (0)

    for (int t = 0; t < SEQ; t += 8) {
#pragma unroll
        for (int u = 0; u < 8; u++) {
            SCAN_STEP(pf[u], t + u);
            pf[u] = (t + 8 + u < SEQ) ? __ldg(gpf + (size_t)u * DIM) : 0.f;
        }
        gpf += 8 * DIM;
    }
#undef SCAN_STEP
}

// ---------------------------------------------------------------------------
// Row scale: g_scale[row] = rsqrt(mean(states^2) + eps), reading fp16 states
// ---------------------------------------------------------------------------
__global__ __launch_bounds__(256) void row_scale_kernel()
{
    const int row = blockIdx.x;
    const __half* p = g_s + (size_t)row * DIM;
    const int t = threadIdx.x;

    const uint4 u = ((const uint4*)p)[t];   // 8 halfs
    const __half2* hp = (const __half2*)&u;
    float ss = 0.f;
#pragma unroll
    for (int i = 0; i < 4; i++) {
        float2 f = __half22float2(hp[i]);
        ss += f.x * f.x + f.y * f.y;
    }

#pragma unroll
    for (int off = 16; off > 0; off >>= 1)
        ss += __shfl_xor_sync(0xFFFFFFFFu, ss, off);

    __shared__ float red[8];
    const int warp = t >> 5;
    const int lane = t & 31;
    if (lane == 0) red[warp] = ss;
    __syncthreads();
    if (warp == 0) {
        float v = (lane < 8) ? red[lane] : 0.f;
#pragma unroll
        for (int off = 4; off > 0; off >>= 1)
            v += __shfl_xor_sync(0xFFFFFFFFu, v, off);
        if (lane == 0) g_scale[row] = rsqrtf(v * (1.0f / DIM) + 1e-6f);
    }
}

// ---------------------------------------------------------------------------
// Launch
// ---------------------------------------------------------------------------
extern "C" void kernel_launch(void* const* d_in, const int* in_sizes, int n_in,
                              void* d_out, int out_size)
{
    const float* x            = (const float*)d_in[0];
    const float* w_in         = (const float*)d_in[1];
    const float* b_in         = (const float*)d_in[2];
    const float* state_weight = (const float*)d_in[3];
    const float* norm_weight  = (const float*)d_in[4];
    const float* w_out        = (const float*)d_in[5];
    float* out = (float*)d_out;

    __half *gx, *gw1, *gw2, *gs;
    float *gh, *gscale;
    cudaGetSymbolAddress((void**)&gx,  g_x);
    cudaGetSymbolAddress((void**)&gw1, g_w1);
    cudaGetSymbolAddress((void**)&gw2, g_w2);
    cudaGetSymbolAddress((void**)&gh,  g_h);
    cudaGetSymbolAddress((void**)&gs,  g_s);
    cudaGetSymbolAddress((void**)&gscale, g_scale);

    const int SMEM_TOTAL = (int)sizeof(Stage) * NSTAGE;   // 61440
    cudaFuncSetAttribute(gemm_h_kernel,
                         cudaFuncAttributeMaxDynamicSharedMemorySize, SMEM_TOTAL);

    // fp16 operand prep (norm_weight folded into w_out)
    cvt_h_kernel<<<(MTOT * DIM) / 2048, 256>>>(x, gx);
    cvt_h_kernel<<<(DIM * DIM) / 2048, 256>>>(w_in, gw1);
    cvt_h_colscale_kernel<<<(DIM * DIM) / 2048, 256>>>(w_out, norm_weight, gw2);

    dim3 ggrid(DIM / GBN, MTOT / GBM);   // (16, 64)

    gemm_h_kernel<<<ggrid, 256, SMEM_TOTAL>>>(gx, gw1, b_in, gh, nullptr);
    rnn_scan_kernel<<<BATCH * NHEADS, 256>>>(state_weight);
    row_scale_kernel<<<MTOT, 256>>>();
    gemm_h_kernel<<<ggrid, 256, SMEM_TOTAL>>>(gs, gw2, nullptr, out, gscale);
}

// round 7
// speedup vs baseline: 4.2785x; 1.2423x over previous
#include <cuda_runtime.h>
#include <cuda_fp16.h>
#include <math.h>
#include <stdint.h>

// Problem constants
#define BATCH 4
#define SEQ   2048
#define DIM   2048
#define NHEADS 32
#define HDIM  64
#define MTOT  (BATCH * SEQ) // 8192

// Scratch (device globals: allocation-free)
__device__ float  g_h[(size_t)MTOT * DIM];   // input-projection output (f32)
__device__ __half g_s[(size_t)MTOT * DIM];   // rnn states (fp16)
__device__ __half g_x[(size_t)MTOT * DIM];   // x (fp16)
__device__ __half g_w1[(size_t)DIM * DIM];   // w_in (fp16)
__device__ __half g_w2[(size_t)DIM * DIM];   // w_out * norm_weight (fp16)
__device__ float  g_scale[MTOT];             // per-row rmsnorm scale

// ---------------------------------------------------------------------------
// helpers
// ---------------------------------------------------------------------------
__device__ __forceinline__ uint32_t smem_u32(const void* p) {
    uint32_t a;
    asm("{ .reg .u64 t; cvta.to.shared.u64 t, %1; cvt.u32.u64 %0, t; }"
        : "=r"(a) : "l"(p));
    return a;
}

#define CP_ASYNC16(dst, src) \
    asm volatile("cp.async.cg.shared.global [%0], [%1], 16;" \
                 :: "r"(dst), "l"(src) : "memory")
#define CP_COMMIT() asm volatile("cp.async.commit_group;" ::: "memory")
#define CP_WAIT(n)  asm volatile("cp.async.wait_group %0;" :: "n"(n) : "memory")

__device__ __forceinline__ void mma_f16(float c[4],
    unsigned a0, unsigned a1, unsigned a2, unsigned a3,
    unsigned b0, unsigned b1)
{
    asm volatile(
        "mma.sync.aligned.m16n8k16.row.col.f32.f16.f16.f32 "
        "{%0,%1,%2,%3}, {%4,%5,%6,%7}, {%8,%9}, {%0,%1,%2,%3};"
        : "+f"(c[0]), "+f"(c[1]), "+f"(c[2]), "+f"(c[3])
        : "r"(a0), "r"(a1), "r"(a2), "r"(a3), "r"(b0), "r"(b1));
}

__device__ __forceinline__ void ldsm_x4(
    unsigned& r0, unsigned& r1, unsigned& r2, unsigned& r3, uint32_t addr)
{
    asm volatile(
        "ldmatrix.sync.aligned.m8n8.x4.shared.b16 {%0,%1,%2,%3}, [%4];"
        : "=r"(r0), "=r"(r1), "=r"(r2), "=r"(r3) : "r"(addr));
}

// ---------------------------------------------------------------------------
// FP16 mma.sync GEMM (fp32 accumulate), cp.async 3-stage, 1 sync/chunk,
// 2 CTAs/SM, ldmatrix fragment loads.
// C[m][n] = (bias[n] +) rowScale[m] * sum_k A[m][k]*B[n][k]
// A (M,K), B (N,K) row-major fp16. CTA tile 128x128, BK=32 (2 k16-steps),
// 256 thr = 8 warps (2M x 4N), warp tile 64x32.
// ---------------------------------------------------------------------------
#define GBM 128
#define GBN 128
#define GBK 32
#define NSTAGE 3
#define SKH 40               // 32 + 8 halfs pad; 80B row stride -> ldsm conflict-free
#define NCHUNK (DIM / GBK)   // 64

struct Stage {
    __half a[GBM][SKH];      // 10240 B
    __half b[GBN][SKH];      // 10240 B
};

__global__ __launch_bounds__(256, 2)
void gemm_h_kernel(const __half* __restrict__ A, const __half* __restrict__ B,
                   const float* __restrict__ bias, float* __restrict__ C,
                   const float* __restrict__ rowScale)
{
    extern __shared__ Stage stg[];   // [NSTAGE]

    const int tid  = threadIdx.x;
    const int lane = tid & 31;
    const int wid  = tid >> 5;
    const int cRow = blockIdx.y * GBM;
    const int cCol = blockIdx.x * GBN;

    const int m0  = (wid & 1) * 64;
    const int n0  = (wid >> 1) * 32;
    const int gid = lane >> 2;   // 0..7
    const int tg  = lane & 3;    // 0..3

    // ldmatrix per-lane source row/col offsets
    const int aRowOff = lane & 15;            // rows m..m+15
    const int aColOff = (lane >> 4) * 8;      // klo/khi
    const int bRowOff = ((lane >> 4) & 1) * 8 + (lane & 7);  // nf pair row
    const int bColOff = ((lane >> 3) & 1) * 8;               // klo/khi

    float acc[4][4][4];
#pragma unroll
    for (int mf = 0; mf < 4; mf++)
#pragma unroll
        for (int nf = 0; nf < 4; nf++)
#pragma unroll
            for (int i = 0; i < 4; i++) acc[mf][nf][i] = 0.f;

    // loader: row = tid>>2 (+64), slot = tid&3 (8 halfs = 16B per cp)
    const int lrow  = tid >> 2;
    const int lslot = tid & 3;
    auto load_chunk = [&](int c, int s) {
        if (c < NCHUNK) {
            const long kOff = (long)c * GBK + 8 * lslot;
#pragma unroll
            for (int i = 0; i < 2; i++) {
                const int row = lrow + 64 * i;
                CP_ASYNC16(smem_u32(&stg[s].a[row][8 * lslot]),
                           A + (size_t)(cRow + row) * DIM + kOff);
                CP_ASYNC16(smem_u32(&stg[s].b[row][8 * lslot]),
                           B + (size_t)(cCol + row) * DIM + kOff);
            }
        }
        CP_COMMIT();
    };

    for (int s = 0; s < NSTAGE - 1; s++) load_chunk(s, s);

    for (int c = 0; c < NCHUNK; c++) {
        const int s = c % NSTAGE;
        CP_WAIT(NSTAGE - 2);
        __syncthreads();
        load_chunk(c + NSTAGE - 1, (c + NSTAGE - 1) % NSTAGE);

        const __half(*As)[SKH] = stg[s].a;
        const __half(*Bs)[SKH] = stg[s].b;

#pragma unroll
        for (int ks = 0; ks < 2; ks++) {       // two k16 steps per chunk
            const int kb = 16 * ks;
            unsigned a[4][4], b[4][2];
#pragma unroll
            for (int mf = 0; mf < 4; mf++) {
                const uint32_t addr = smem_u32(
                    &As[m0 + 16 * mf + aRowOff][kb + aColOff]);
                ldsm_x4(a[mf][0], a[mf][1], a[mf][2], a[mf][3], addr);
            }
#pragma unroll
            for (int p = 0; p < 2; p++) {
                const uint32_t addr = smem_u32(
                    &Bs[n0 + 16 * p + bRowOff][kb + bColOff]);
                ldsm_x4(b[2 * p][0], b[2 * p][1], b[2 * p + 1][0], b[2 * p + 1][1], addr);
            }
#pragma unroll
            for (int mf = 0; mf < 4; mf++)
#pragma unroll
                for (int nf = 0; nf < 4; nf++)
                    mma_f16(acc[mf][nf], a[mf][0], a[mf][1], a[mf][2], a[mf][3],
                            b[nf][0], b[nf][1]);
        }
    }

    // epilogue: c0/c1 at (row, 2tg..), c2/c3 at (row+8, ..)
#pragma unroll
    for (int mf = 0; mf < 4; mf++) {
        const int row = cRow + m0 + 16 * mf + gid;
        const float rs0 = rowScale ? rowScale[row] : 1.f;
        const float rs1 = rowScale ? rowScale[row + 8] : 1.f;
#pragma unroll
        for (int nf = 0; nf < 4; nf++) {
            const int col = cCol + n0 + 8 * nf + 2 * tg;
            float b0 = 0.f, b1 = 0.f;
            if (bias) { b0 = bias[col]; b1 = bias[col + 1]; }
            float2 v0 = make_float2(acc[mf][nf][0] * rs0 + b0, acc[mf][nf][1] * rs0 + b1);
            float2 v1 = make_float2(acc[mf][nf][2] * rs1 + b0, acc[mf][nf][3] * rs1 + b1);
            *(float2*)(C + (size_t)row * DIM + col) = v0;
            *(float2*)(C + (size_t)(row + 8) * DIM + col) = v1;
        }
    }
}

// ---------------------------------------------------------------------------
// f32 -> fp16 conversions (8 elems/thread); colscale folds norm_weight
// ---------------------------------------------------------------------------
__global__ __launch_bounds__(256) void cvt_h_kernel(
    const float* __restrict__ in, __half* __restrict__ out)
{
    const size_t i = ((size_t)blockIdx.x * 256 + threadIdx.x) * 8;
    const float4 v0 = *(const float4*)(in + i);
    const float4 v1 = *(const float4*)(in + i + 4);
    __half2 h[4];
    h[0] = __floats2half2_rn(v0.x, v0.y);
    h[1] = __floats2half2_rn(v0.z, v0.w);
    h[2] = __floats2half2_rn(v1.x, v1.y);
    h[3] = __floats2half2_rn(v1.z, v1.w);
    *(uint4*)(out + i) = *(const uint4*)h;
}

__global__ __launch_bounds__(256) void cvt_h_colscale_kernel(
    const float* __restrict__ in, const float* __restrict__ colw,
    __half* __restrict__ out)
{
    const size_t i = ((size_t)blockIdx.x * 256 + threadIdx.x) * 8;
    const int c = (int)(i & (DIM - 1));
    const float4 v0 = *(const float4*)(in + i);
    const float4 v1 = *(const float4*)(in + i + 4);
    const float4 g0 = *(const float4*)(colw + c);
    const float4 g1 = *(const float4*)(colw + c + 4);
    __half2 h[4];
    h[0] = __floats2half2_rn(v0.x * g0.x, v0.y * g0.y);
    h[1] = __floats2half2_rn(v0.z * g0.z, v0.w * g0.w);
    h[2] = __floats2half2_rn(v1.x * g1.x, v1.y * g1.y);
    h[3] = __floats2half2_rn(v1.z * g1.z, v1.w * g1.w);
    *(uint4*)(out + i) = *(const uint4*)h;
}

// ---------------------------------------------------------------------------
// RNN scan: pair-split (proven fastest). 128 threads; pair (2j,2j+1) owns
// output j, 32 MACs each + one shfl. Depth-8 input prefetch, fp16 stores.
// ---------------------------------------------------------------------------
__global__ __launch_bounds__(128) void rnn_scan_kernel(
    const float* __restrict__ state_weight)
{
    const int b = blockIdx.x >> 5;
    const int n = blockIdx.x & 31;
    const int tid = threadIdx.x;
    const int j = tid >> 1;
    const int half = tid & 1;

    __shared__ float s_sh[2][HDIM];

    float Wc[32];
    const float* Wn = state_weight + (size_t)n * HDIM * HDIM;
#pragma unroll
    for (int k = 0; k < 32; k++)
        Wc[k] = Wn[(32 * half + k) * HDIM + j];

    if (half == 0) s_sh[0][j] = 0.f;
    __syncthreads();

    const size_t base = ((size_t)b * SEQ) * DIM + n * HDIM + j;
    const float* gin = g_h + base;
    __half* gout = g_s + base;

    float pf[8];
#pragma unroll
    for (int u = 0; u < 8; u++) pf[u] = __ldg(gin + (size_t)u * DIM);
    const float* gpf = gin + 8 * DIM;

    int cur = 0;

#define SCAN_STEP(XT, T)                                                     \
    do {                                                                     \
        const float4* sp = (const float4*)&s_sh[cur][32 * half];             \
        float a0 = 0.f, a1 = 0.f, a2 = 0.f, a3 = 0.f;                        \
        _Pragma("unroll")                                                    \
        for (int k4 = 0; k4 < 8; k4++) {                                     \
            float4 v = sp[k4];                                               \
            a0 = fmaf(v.x, Wc[4 * k4 + 0], a0);                              \
            a1 = fmaf(v.y, Wc[4 * k4 + 1], a1);                              \
            a2 = fmaf(v.z, Wc[4 * k4 + 2], a2);                              \
            a3 = fmaf(v.w, Wc[4 * k4 + 3], a3);                              \
        }                                                                    \
        float p = (a0 + a1) + (a2 + a3);                                     \
        p += __shfl_xor_sync(0xFFFFFFFFu, p, 1);                             \
        float z = p + (XT);                                                  \
        float e = __expf(2.f * z);                                           \
        float sv = 1.f - __fdividef(2.f, e + 1.f);                           \
        if (half == 0) s_sh[cur ^ 1][j] = sv;                                \
        else           gout[(size_t)(T) * DIM] = __float2half_rn(sv);        \
        cur ^= 1;                                                            \
        __syncthreads();                                                     \
    } while (0)

    for (int t = 0; t < SEQ; t += 8) {
#pragma unroll
        for (int u = 0; u < 8; u++) {
            SCAN_STEP(pf[u], t + u);
            pf[u] = (t + 8 + u < SEQ) ? __ldg(gpf + (size_t)u * DIM) : 0.f;
        }
        gpf += 8 * DIM;
    }
#undef SCAN_STEP
}

// ---------------------------------------------------------------------------
// Row scale: g_scale[row] = rsqrt(mean(states^2) + eps), reading fp16 states
// ---------------------------------------------------------------------------
__global__ __launch_bounds__(256) void row_scale_kernel()
{
    const int row = blockIdx.x;
    const __half* p = g_s + (size_t)row * DIM;
    const int t = threadIdx.x;

    const uint4 u = ((const uint4*)p)[t];   // 8 halfs
    const __half2* hp = (const __half2*)&u;
    float ss = 0.f;
#pragma unroll
    for (int i = 0; i < 4; i++) {
        float2 f = __half22float2(hp[i]);
        ss += f.x * f.x + f.y * f.y;
    }

#pragma unroll
    for (int off = 16; off > 0; off >>= 1)
        ss += __shfl_xor_sync(0xFFFFFFFFu, ss, off);

    __shared__ float red[8];
    const int warp = t >> 5;
    const int lane = t & 31;
    if (lane == 0) red[warp] = ss;
    __syncthreads();
    if (warp == 0) {
        float v = (lane < 8) ? red[lane] : 0.f;
#pragma unroll
        for (int off = 4; off > 0; off >>= 1)
            v += __shfl_xor_sync(0xFFFFFFFFu, v, off);
        if (lane == 0) g_scale[row] = rsqrtf(v * (1.0f / DIM) + 1e-6f);
    }
}

// ---------------------------------------------------------------------------
// Launch
// ---------------------------------------------------------------------------
extern "C" void kernel_launch(void* const* d_in, const int* in_sizes, int n_in,
                              void* d_out, int out_size)
{
    const float* x            = (const float*)d_in[0];
    const float* w_in         = (const float*)d_in[1];
    const float* b_in         = (const float*)d_in[2];
    const float* state_weight = (const float*)d_in[3];
    const float* norm_weight  = (const float*)d_in[4];
    const float* w_out        = (const float*)d_in[5];
    float* out = (float*)d_out;

    __half *gx, *gw1, *gw2, *gs;
    float *gh, *gscale;
    cudaGetSymbolAddress((void**)&gx,  g_x);
    cudaGetSymbolAddress((void**)&gw1, g_w1);
    cudaGetSymbolAddress((void**)&gw2, g_w2);
    cudaGetSymbolAddress((void**)&gh,  g_h);
    cudaGetSymbolAddress((void**)&gs,  g_s);
    cudaGetSymbolAddress((void**)&gscale, g_scale);

    const int SMEM_TOTAL = (int)sizeof(Stage) * NSTAGE;   // 61440
    cudaFuncSetAttribute(gemm_h_kernel,
                         cudaFuncAttributeMaxDynamicSharedMemorySize, SMEM_TOTAL);

    // fp16 operand prep (norm_weight folded into w_out)
    cvt_h_kernel<<<(MTOT * DIM) / 2048, 256>>>(x, gx);
    cvt_h_kernel<<<(DIM * DIM) / 2048, 256>>>(w_in, gw1);
    cvt_h_colscale_kernel<<<(DIM * DIM) / 2048, 256>>>(w_out, norm_weight, gw2);

    dim3 ggrid(DIM / GBN, MTOT / GBM);   // (16, 64)

    gemm_h_kernel<<<ggrid, 256, SMEM_TOTAL>>>(gx, gw1, b_in, gh, nullptr);
    rnn_scan_kernel<<<BATCH * NHEADS, 128>>>(state_weight);
    row_scale_kernel<<<MTOT, 256>>>();
    gemm_h_kernel<<<ggrid, 256, SMEM_TOTAL>>>(gs, gw2, nullptr, out, gscale);
}